// round 3
// baseline (speedup 1.0000x reference)
#include <cuda_runtime.h>
#include <cuda_bf16.h>

// Single-fused-kernel collision pipeline.
// N=8192 bodies in BOX=112, radii in [0.5,1.0) -> rsum < 2.0.
// Spatial grid cell=2.0 (56x56): overlapping pairs are within +-1 cell ring
// (floor(a*0.5) vs floor(b*0.5) differ by <=1 when |a-b| < 2.0).
// Reference semantics: row-major ascending (i,j) compaction with hard cutoffs
// (limit_broad=4N candidates, limit_narrow=N hits) -> reproduced via exact
// global rank computation (sorted per-row lists + block prefix scan).

#define MAXN  8192
#define MAXB  (4 * MAXN)
#define GDIM  56
#define NCELL (GDIM * GDIM)
#define CAP   32            // per-row candidate cap (avg ~4; Poisson tail safe)
#define NTHR  1024
#define BPT   (MAXN / NTHR) // 8 bodies per thread, contiguous rows

__device__ float4        g_cellbody[MAXN];      // x, y, r, body index bits
__device__ int           g_rowbuf[MAXN * CAP];  // sorted j's per row
__device__ int           g_pair[MAXB];          // (i<<16)|j
__device__ unsigned char g_hit[MAXB];
__device__ float2        g_delta[MAXB];         // 0.5 * penetration vector

__global__ __launch_bounds__(NTHR)
void collide_mega_kernel(const float2* __restrict__ c,
                         const float*  __restrict__ r,
                         const int*    __restrict__ d_lb,
                         const int*    __restrict__ d_ln,
                         float*        __restrict__ out, int n) {
    __shared__ int s_cellcnt[NCELL];
    __shared__ int s_cellstart[NCELL];
    __shared__ int s_cellfill[NCELL];
    __shared__ int s_scan[NTHR];
    __shared__ int s_total;

    const int t = threadIdx.x;

    // ---- P0: out = centers (coalesced float2 copy) + zero cell counts ----
    {
        const float2* src = c;
        float2* dst = (float2*)out;
        for (int k = t; k < n; k += NTHR) dst[k] = src[k];
        for (int k = t; k < NCELL; k += NTHR) s_cellcnt[k] = 0;
    }
    __syncthreads();

    // ---- P1: load my bodies, histogram cells ----
    float2 pc[BPT]; float pr[BPT]; int pcell[BPT];
    #pragma unroll
    for (int k = 0; k < BPT; k++) {
        int i = t * BPT + k;
        if (i < n) {
            float2 ci = c[i];
            pc[k] = ci; pr[k] = r[i];
            int cx = min(GDIM - 1, max(0, (int)(ci.x * 0.5f)));
            int cy = min(GDIM - 1, max(0, (int)(ci.y * 0.5f)));
            int cell = cy * GDIM + cx;
            pcell[k] = cell;
            atomicAdd(&s_cellcnt[cell], 1);
        } else {
            pc[k] = make_float2(0.f, 0.f); pr[k] = 0.f; pcell[k] = -1;
        }
    }
    __syncthreads();

    // ---- P2: exclusive scan of cell counts ----
    {
        int local[4]; int sum = 0;
        int base = t * 4;                  // 4096 slots >= 3136 cells
        #pragma unroll
        for (int k = 0; k < 4; k++) {
            int idx = base + k;
            int v = (idx < NCELL) ? s_cellcnt[idx] : 0;
            local[k] = sum; sum += v;
        }
        s_scan[t] = sum;
        __syncthreads();
        for (int o = 1; o < NTHR; o <<= 1) {
            int x = (t >= o) ? s_scan[t - o] : 0;
            __syncthreads();
            s_scan[t] += x;
            __syncthreads();
        }
        int excl = s_scan[t] - sum;
        #pragma unroll
        for (int k = 0; k < 4; k++) {
            int idx = base + k;
            if (idx < NCELL) {
                int st = excl + local[k];
                s_cellstart[idx] = st;
                s_cellfill[idx]  = st;
            }
        }
    }
    __syncthreads();

    // ---- P3: counting-sort scatter of bodies into cell order ----
    #pragma unroll
    for (int k = 0; k < BPT; k++) {
        int i = t * BPT + k;
        if (i < n) {
            int slot = atomicAdd(&s_cellfill[pcell[k]], 1);
            g_cellbody[slot] = make_float4(pc[k].x, pc[k].y, pr[k],
                                           __int_as_float(i));
        }
    }
    __syncthreads();

    // ---- P4: broad phase per row: 3x3 ring query, sorted candidate list ----
    int rowcnt[BPT];
    #pragma unroll
    for (int k = 0; k < BPT; k++) {
        int i = t * BPT + k;
        int cnt = 0;
        if (i < n) {
            float2 ci = pc[k]; float ri = pr[k];
            int cx = pcell[k] % GDIM, cy = pcell[k] / GDIM;
            int jl[CAP];
            int y0 = max(cy - 1, 0), y1 = min(cy + 1, GDIM - 1);
            int x0 = max(cx - 1, 0), x1 = min(cx + 1, GDIM - 1);
            for (int yy = y0; yy <= y1; yy++)
            for (int xx = x0; xx <= x1; xx++) {
                int cell = yy * GDIM + xx;
                int st = s_cellstart[cell];
                int en = st + s_cellcnt[cell];
                for (int q = st; q < en; q++) {
                    float4 b = g_cellbody[q];
                    int j = __float_as_int(b.w);
                    if (j <= i) continue;
                    float rs = ri + b.z;
                    if (fabsf(ci.x - b.x) <= rs && fabsf(ci.y - b.y) <= rs) {
                        if (cnt < CAP) jl[cnt] = j;
                        cnt++;
                    }
                }
            }
            if (cnt > CAP) cnt = CAP;
            // insertion sort ascending
            for (int a = 1; a < cnt; a++) {
                int v = jl[a]; int b2 = a - 1;
                while (b2 >= 0 && jl[b2] > v) { jl[b2 + 1] = jl[b2]; b2--; }
                jl[b2 + 1] = v;
            }
            for (int q = 0; q < cnt; q++) g_rowbuf[i * CAP + q] = jl[q];
        }
        rowcnt[k] = cnt;
    }

    // ---- P5: global row-offset scan (registers + block scan) ----
    int rowoff[BPT];
    {
        int sum = 0;
        #pragma unroll
        for (int k = 0; k < BPT; k++) { rowoff[k] = sum; sum += rowcnt[k]; }
        __syncthreads();               // protect s_scan reuse
        s_scan[t] = sum;
        __syncthreads();
        for (int o = 1; o < NTHR; o <<= 1) {
            int x = (t >= o) ? s_scan[t - o] : 0;
            __syncthreads();
            s_scan[t] += x;
            __syncthreads();
        }
        int excl = s_scan[t] - sum;
        #pragma unroll
        for (int k = 0; k < BPT; k++) rowoff[k] += excl;
        if (t == NTHR - 1) s_total = s_scan[NTHR - 1];
    }
    __syncthreads();

    const int limitb = min(*d_lb, MAXB);
    const int tot = min(s_total, limitb);

    // ---- P6: emit pairs at exact ranks + fused narrow phase ----
    #pragma unroll
    for (int k = 0; k < BPT; k++) {
        int i = t * BPT + k;
        if (i >= n) break;
        int off = rowoff[k], cnt = rowcnt[k];
        if (off >= limitb) break;      // offsets nondecreasing across k
        float2 ci = pc[k]; float ri = pr[k];
        for (int q = 0; q < cnt; q++) {
            int slot = off + q;
            if (slot >= limitb) break;
            int j = g_rowbuf[i * CAP + q];
            float2 cj = c[j];
            float dx = cj.x - ci.x;
            float dy = cj.y - ci.y;
            float dist = sqrtf(dx * dx + dy * dy + 1e-12f);
            float depth = ri + r[j] - dist;
            unsigned char hit = 0;
            float2 del = make_float2(0.f, 0.f);
            if (depth > 0.f) {
                hit = 1;
                float sc = 0.5f * depth / dist;
                del = make_float2(sc * dx, sc * dy);
            }
            g_pair[slot]  = (i << 16) | j;
            g_hit[slot]   = hit;
            g_delta[slot] = del;
        }
    }
    __syncthreads();

    // ---- P7: ordered hit compaction (scan) + scatter resolve ----
    {
        const int ln = *d_ln;
        const int items = (tot + NTHR - 1) / NTHR;
        const int start = t * items;
        const int end   = min(start + items, tot);
        int sum = 0;
        for (int k = start; k < end; k++) sum += g_hit[k];
        s_scan[t] = sum;
        __syncthreads();
        for (int o = 1; o < NTHR; o <<= 1) {
            int x = (t >= o) ? s_scan[t - o] : 0;
            __syncthreads();
            s_scan[t] += x;
            __syncthreads();
        }
        int rank = s_scan[t] - sum;    // exclusive prefix of my chunk
        for (int k = start; k < end; k++) {
            if (g_hit[k]) {
                if (rank < ln) {
                    int p = g_pair[k];
                    int i = p >> 16;
                    int j = p & 0xFFFF;
                    float2 d = g_delta[k];
                    atomicAdd(&out[2 * i + 0], -d.x);
                    atomicAdd(&out[2 * i + 1], -d.y);
                    atomicAdd(&out[2 * j + 0],  d.x);
                    atomicAdd(&out[2 * j + 1],  d.y);
                }
                rank++;
            }
        }
    }
}

// ---------------------------------------------------------------------------
extern "C" void kernel_launch(void* const* d_in, const int* in_sizes, int n_in,
                              void* d_out, int out_size) {
    const float2* centers = (const float2*)d_in[0];
    const float*  radii   = (const float*)d_in[1];
    const int*    d_lb    = (const int*)d_in[2];
    const int*    d_ln    = (const int*)d_in[3];
    const int n = in_sizes[1];           // number of bodies
    float* out = (float*)d_out;

    collide_mega_kernel<<<1, NTHR>>>(centers, radii, d_lb, d_ln, out, n);
}

// round 4
// speedup vs baseline: 5.4964x; 5.4964x over previous
#include <cuda_runtime.h>
#include <cuda_bf16.h>

// One-kernel collision pipeline, 32 blocks x 256 threads (1 body/thread),
// software global barriers between phases.
// N=8192, BOX=112, radii in [0.5,1.0) -> rsum < 2.0 -> grid cell 2.0 (56x56),
// all AABB-overlapping pairs lie in the +-1 cell ring.
// Reference semantics: row-major ascending (i,j) compaction, cutoffs 4N / N.

#define MAXN  8192
#define MAXB  (4 * MAXN)
#define GDIM  56
#define NCELL (GDIM * GDIM)
#define CAPC  20            // bodies per cell (avg 2.6, Poisson tail safe)
#define CAPR  32            // candidates per row (avg ~4-8, Poisson tail safe)
#define NBLK  32
#define NTPB  256
#define NTH   (NBLK * NTPB)

__device__ unsigned      g_bar_cnt = 0;          // self-resetting
__device__ unsigned      g_bar_epoch = 0;        // monotonic across replays
__device__ int           g_cellcnt[NCELL];       // zero-init, self-cleaning
__device__ float4        g_cellslot[NCELL * CAPC];
__device__ int           g_bsum[NBLK];
__device__ int           g_hsum[NBLK];
__device__ int           g_pair[MAXB];           // (i<<16)|j
__device__ unsigned char g_hit[MAXB];
__device__ float2        g_delta[MAXB];

__device__ __forceinline__ void global_barrier() {
    __syncthreads();
    if (threadIdx.x == 0) {
        volatile unsigned* ep = &g_bar_epoch;
        unsigned e = *ep;
        __threadfence();
        unsigned old = atomicAdd(&g_bar_cnt, 1u);
        if (old == gridDim.x - 1) {
            g_bar_cnt = 0;
            __threadfence();
            atomicAdd(&g_bar_epoch, 1u);
        } else {
            while (*ep == e) __nanosleep(32);
        }
        __threadfence();
    }
    __syncthreads();
}

// Exclusive block scan over NTPB values; also returns block total via smem.
__device__ __forceinline__ int block_scan_excl(int v, int* s_ws, int* btot) {
    const int t = threadIdx.x, lane = t & 31, wid = t >> 5;
    int incl = v;
    #pragma unroll
    for (int o = 1; o < 32; o <<= 1) {
        int x = __shfl_up_sync(0xFFFFFFFFu, incl, o);
        if (lane >= o) incl += x;
    }
    if (lane == 31) s_ws[wid] = incl;
    __syncthreads();
    if (wid == 0) {
        int w = (lane < NTPB / 32) ? s_ws[lane] : 0;
        int iw = w;
        #pragma unroll
        for (int o = 1; o < 32; o <<= 1) {
            int x = __shfl_up_sync(0xFFFFFFFFu, iw, o);
            if (lane >= o) iw += x;
        }
        if (lane < NTPB / 32) s_ws[lane] = iw - w;       // exclusive
        if (lane == NTPB / 32 - 1) s_ws[NTPB / 32] = iw; // total
    }
    __syncthreads();
    *btot = s_ws[NTPB / 32];
    return incl - v + s_ws[wid];
}

__global__ __launch_bounds__(NTPB)
void collide_kernel(const float2* __restrict__ c,
                    const float*  __restrict__ r,
                    const int*    __restrict__ d_lb,
                    const int*    __restrict__ d_ln,
                    float*        __restrict__ out, int n) {
    __shared__ int s_ws[NTPB / 32 + 1];
    const int t   = threadIdx.x;
    const int bid = blockIdx.x;
    const int gid = bid * NTPB + t;

    // ---- P1: load body, copy to out, insert into grid ----
    float2 ci = make_float2(0.f, 0.f);
    float  ri = 0.f;
    int mycell = 0;
    if (gid < n) {
        ci = c[gid];
        ri = r[gid];
        ((float2*)out)[gid] = ci;
        int cx = min(GDIM - 1, max(0, (int)(ci.x * 0.5f)));
        int cy = min(GDIM - 1, max(0, (int)(ci.y * 0.5f)));
        mycell = cy * GDIM + cx;
        int slot = atomicAdd(&g_cellcnt[mycell], 1);
        if (slot < CAPC)
            g_cellslot[mycell * CAPC + slot] =
                make_float4(ci.x, ci.y, ri, __int_as_float(gid));
    }
    global_barrier();   // GB1: grid built

    // ---- P2: ring query -> register candidate list ----
    int jl[CAPR];
    int cnt = 0;
    if (gid < n) {
        int cx = mycell % GDIM, cy = mycell / GDIM;
        int y0 = max(cy - 1, 0), y1 = min(cy + 1, GDIM - 1);
        int x0 = max(cx - 1, 0), x1 = min(cx + 1, GDIM - 1);
        for (int yy = y0; yy <= y1; yy++)
        for (int xx = x0; xx <= x1; xx++) {
            int cell = yy * GDIM + xx;
            int cc = min(g_cellcnt[cell], CAPC);
            for (int q = 0; q < cc; q++) {
                float4 b = g_cellslot[cell * CAPC + q];
                int j = __float_as_int(b.w);
                if (j <= gid) continue;
                float rs = ri + b.z;
                if (fabsf(ci.x - b.x) <= rs && fabsf(ci.y - b.y) <= rs) {
                    if (cnt < CAPR) {
                        #pragma unroll
                        for (int k = 0; k < CAPR; k++)
                            if (k == cnt) jl[k] = j;
                    }
                    cnt++;
                }
            }
        }
        if (cnt > CAPR) cnt = CAPR;
    }

    // ---- P3: global row-offset scan ----
    int btot;
    int excl = block_scan_excl(cnt, s_ws, &btot);
    if (t == 0) g_bsum[bid] = btot;
    global_barrier();   // GB2: block sums published

    int pre = 0, totalc = 0;
    #pragma unroll
    for (int b = 0; b < NBLK; b++) {
        int s = g_bsum[b];
        totalc += s;
        if (b < bid) pre += s;
    }
    const int off    = pre + excl;
    const int limitb = min(*d_lb, MAXB);
    const int totp   = min(totalc, limitb);

    // self-clean cell counts for next replay (cellcnt no longer needed)
    for (int idx = gid; idx < NCELL; idx += NTH) g_cellcnt[idx] = 0;

    // ---- P4: emit at exact global ranks + fused narrow phase ----
    if (gid < n) {
        #pragma unroll
        for (int k = 0; k < CAPR; k++) {
            if (k >= cnt) break;
            int v = jl[k];
            int rank = 0;
            #pragma unroll
            for (int m = 0; m < CAPR; m++) {
                if (m >= cnt) break;
                rank += (jl[m] < v);
            }
            int slot = off + rank;
            if (slot < limitb) {
                float2 cj = c[v];
                float dx = cj.x - ci.x;
                float dy = cj.y - ci.y;
                float dist = sqrtf(dx * dx + dy * dy + 1e-12f);
                float depth = ri + r[v] - dist;
                unsigned char hit = 0;
                float2 del = make_float2(0.f, 0.f);
                if (depth > 0.f) {
                    hit = 1;
                    float sc = 0.5f * depth / dist;
                    del = make_float2(sc * dx, sc * dy);
                }
                g_pair[slot]  = (gid << 16) | v;
                g_hit[slot]   = hit;
                g_delta[slot] = del;
            }
        }
    }
    global_barrier();   // GB3: candidate slots written

    // ---- P5: ordered hit compaction + scatter resolve ----
    const int ln    = *d_ln;
    const int chunk = (totp + NTH - 1) / NTH;
    const int st    = gid * chunk;
    const int en    = min(st + chunk, totp);

    int h = 0;
    for (int k = st; k < en; k++) h += g_hit[k];
    int bhtot;
    int hexcl = block_scan_excl(h, s_ws, &bhtot);
    if (t == 0) g_hsum[bid] = bhtot;
    global_barrier();   // GB4: hit block sums published

    int hpre = 0;
    #pragma unroll
    for (int b = 0; b < NBLK; b++)
        if (b < bid) hpre += g_hsum[b];
    int rank = hpre + hexcl;
    for (int k = st; k < en; k++) {
        if (g_hit[k]) {
            if (rank < ln) {
                int p = g_pair[k];
                int i = p >> 16;
                int j = p & 0xFFFF;
                float2 d = g_delta[k];
                atomicAdd(&out[2 * i + 0], -d.x);
                atomicAdd(&out[2 * i + 1], -d.y);
                atomicAdd(&out[2 * j + 0],  d.x);
                atomicAdd(&out[2 * j + 1],  d.y);
            }
            rank++;
        }
    }
}

// ---------------------------------------------------------------------------
extern "C" void kernel_launch(void* const* d_in, const int* in_sizes, int n_in,
                              void* d_out, int out_size) {
    const float2* centers = (const float2*)d_in[0];
    const float*  radii   = (const float*)d_in[1];
    const int*    d_lb    = (const int*)d_in[2];
    const int*    d_ln    = (const int*)d_in[3];
    const int n = in_sizes[1];
    float* out = (float*)d_out;

    collide_kernel<<<NBLK, NTPB>>>(centers, radii, d_lb, d_ln, out, n);
}

// round 5
// speedup vs baseline: 6.6479x; 1.2095x over previous
#include <cuda_runtime.h>
#include <cuda_bf16.h>

// One-kernel collision pipeline, 64 blocks x 128 threads (1 body/thread),
// 2 software global barriers. Narrow phase fused into the broad-phase ring
// query; hit ranks derived from a single packed (cnt,hitcnt) 64-bit scan, so
// no pair buffers and no second compaction pass are needed.
//
// N=8192, BOX=112, radii in [0.5,1.0) -> rsum < 2.0 -> grid cell 2.0 (56x56);
// all AABB-overlapping pairs lie within the +-1 cell ring.
// Reference semantics: row-major ascending (i,j) candidate order, cutoffs
// limit_broad=4N / limit_narrow=N, reproduced exactly (see rank proofs in
// comments below).

#define MAXN  8192
#define MAXB  (4 * MAXN)
#define GDIM  56
#define NCELL (GDIM * GDIM)
#define CAPC  20            // bodies/cell (observed max <= 20 on this dataset)
#define CAPR  32            // candidates/row (observed max <= 32)
#define NBLK  64
#define NTPB  128
#define NTH   (NBLK * NTPB)

typedef unsigned long long ull;

__device__ unsigned g_bar_cnt = 0;      // self-resetting
__device__ unsigned g_bar_epoch = 0;    // monotonic across graph replays
__device__ int      g_cellcnt[NCELL];   // zero-init, self-cleaning per launch
__device__ float4   g_cellslot[NCELL * CAPC];  // x, y, r, body-index bits
__device__ ull      g_bsum[NBLK];       // packed (cnt<<32 | hitcnt) block sums

__device__ __forceinline__ void global_barrier() {
    __syncthreads();
    if (threadIdx.x == 0) {
        volatile unsigned* ep = &g_bar_epoch;
        unsigned e = *ep;
        __threadfence();
        unsigned old = atomicAdd(&g_bar_cnt, 1u);
        if (old == gridDim.x - 1) {
            g_bar_cnt = 0;
            __threadfence();
            atomicAdd(&g_bar_epoch, 1u);
        } else {
            while (*ep == e) __nanosleep(16);
        }
        __threadfence();
    }
    __syncthreads();
}

// Exclusive block scan over a packed 64-bit value (no cross-field carry:
// both 32-bit sums stay far below 2^32).
__device__ __forceinline__ ull block_scan_excl(ull v, ull* s_ws) {
    const int t = threadIdx.x, lane = t & 31, wid = t >> 5;
    ull incl = v;
    #pragma unroll
    for (int o = 1; o < 32; o <<= 1) {
        ull x = __shfl_up_sync(0xFFFFFFFFu, incl, o);
        if (lane >= o) incl += x;
    }
    if (lane == 31) s_ws[wid] = incl;
    __syncthreads();
    if (wid == 0 && lane == 0) {
        ull run = 0;
        #pragma unroll
        for (int w = 0; w < NTPB / 32; w++) {
            ull x = s_ws[w];
            s_ws[w] = run;          // exclusive warp offsets
            run += x;
        }
        s_ws[NTPB / 32] = run;      // block total
    }
    __syncthreads();
    return incl - v + s_ws[wid];
}

__global__ __launch_bounds__(NTPB)
void collide_kernel(const float2* __restrict__ c,
                    const float*  __restrict__ r,
                    const int*    __restrict__ d_lb,
                    const int*    __restrict__ d_ln,
                    float*        __restrict__ out, int n) {
    __shared__ ull s_ws[NTPB / 32 + 1];
    const int t   = threadIdx.x;
    const int bid = blockIdx.x;
    const int gid = bid * NTPB + t;

    // ---- P1: load body, copy centers to out, insert into grid ----
    float2 ci = make_float2(0.f, 0.f);
    float  ri = 0.f;
    int mycell = 0;
    if (gid < n) {
        ci = c[gid];
        ri = r[gid];
        ((float2*)out)[gid] = ci;
        int cx = min(GDIM - 1, max(0, (int)(ci.x * 0.5f)));
        int cy = min(GDIM - 1, max(0, (int)(ci.y * 0.5f)));
        mycell = cy * GDIM + cx;
        int slot = atomicAdd(&g_cellcnt[mycell], 1);
        if (slot < CAPC)
            g_cellslot[mycell * CAPC + slot] =
                make_float4(ci.x, ci.y, ri, __int_as_float(gid));
    }
    global_barrier();   // GB1: grid built

    // ---- P2: ring query -> register candidates + fused narrow test ----
    int jl[CAPR];
    unsigned hitmask = 0;   // bit k: candidate at storage index k penetrates
    int cnt = 0;
    if (gid < n) {
        int cx = mycell % GDIM, cy = mycell / GDIM;
        int y0 = max(cy - 1, 0), y1 = min(cy + 1, GDIM - 1);
        int x0 = max(cx - 1, 0), x1 = min(cx + 1, GDIM - 1);
        for (int yy = y0; yy <= y1; yy++)
        for (int xx = x0; xx <= x1; xx++) {
            int cell = yy * GDIM + xx;
            int cc = min(g_cellcnt[cell], CAPC);
            const float4* base = &g_cellslot[cell * CAPC];
            for (int q = 0; q < cc; q++) {
                float4 b = base[q];
                int j = __float_as_int(b.w);
                if (j <= gid) continue;
                float rs = ri + b.z;
                float dx = b.x - ci.x;
                float dy = b.y - ci.y;
                if (fabsf(dx) <= rs && fabsf(dy) <= rs) {
                    if (cnt < CAPR) {
                        // narrow phase inline (b carries x,y,r)
                        float dist = sqrtf(dx * dx + dy * dy + 1e-12f);
                        if (rs - dist > 0.f) hitmask |= (1u << cnt);
                        #pragma unroll
                        for (int k = 0; k < CAPR; k++)
                            if (k == cnt) jl[k] = j;
                    }
                    cnt++;
                }
            }
        }
        if (cnt > CAPR) cnt = CAPR;
    }
    const int hitcnt = __popc(hitmask);

    // ---- P3: one packed scan -> candidate offset + global hit rank ----
    ull excl = block_scan_excl(((ull)cnt << 32) | (unsigned)hitcnt, s_ws);
    if (t == 0) g_bsum[bid] = s_ws[NTPB / 32];
    global_barrier();   // GB2: block sums published

    ull pre = 0;
    #pragma unroll
    for (int b = 0; b < NBLK; b++)
        if (b < bid) pre += g_bsum[b];
    const int offc = (int)((pre + excl) >> 32);        // my first candidate slot
    const int offh = (int)((pre + excl) & 0xFFFFFFFFu); // my first hit rank
    const int limitb = min(*d_lb, MAXB);
    const int ln     = *d_ln;

    // self-clean cell counters for the next graph replay
    for (int idx = gid; idx < NCELL; idx += NTH) g_cellcnt[idx] = 0;

    // ---- P4: apply resolve directly for hits within both cutoffs ----
    // Broad cutoff: candidate survives iff its sorted rank < limitb - offc.
    // (If an earlier thread straddles limitb, this thread has offc >= limitb
    //  and emits nothing; dropped candidates are always the highest ranks, so
    //  unmasked hit prefix sums remain exact for every emitting thread.)
    if (gid < n && offc < limitb) {
        const int survive = min(cnt, limitb - offc);
        #pragma unroll
        for (int k = 0; k < CAPR; k++) {
            if (k >= cnt) break;
            if (!((hitmask >> k) & 1u)) continue;
            int jv = jl[k];
            int rank = 0, hrank = 0;
            #pragma unroll
            for (int m = 0; m < CAPR; m++) {
                if (m >= cnt) break;
                bool lt = (jl[m] < jv);
                rank  += lt;
                hrank += lt && ((hitmask >> m) & 1u);
            }
            if (rank >= survive) continue;        // broad cutoff
            if (offh + hrank >= ln) continue;     // narrow cutoff
            float2 cj = c[jv];
            float  rj = r[jv];
            float dx = cj.x - ci.x;
            float dy = cj.y - ci.y;
            float dist = sqrtf(dx * dx + dy * dy + 1e-12f);
            float sc = 0.5f * (ri + rj - dist) / dist;
            float ddx = sc * dx, ddy = sc * dy;
            atomicAdd(&out[2 * gid + 0], -ddx);
            atomicAdd(&out[2 * gid + 1], -ddy);
            atomicAdd(&out[2 * jv  + 0],  ddx);
            atomicAdd(&out[2 * jv  + 1],  ddy);
        }
    }
}

// ---------------------------------------------------------------------------
extern "C" void kernel_launch(void* const* d_in, const int* in_sizes, int n_in,
                              void* d_out, int out_size) {
    const float2* centers = (const float2*)d_in[0];
    const float*  radii   = (const float*)d_in[1];
    const int*    d_lb    = (const int*)d_in[2];
    const int*    d_ln    = (const int*)d_in[3];
    const int n = in_sizes[1];
    float* out = (float*)d_out;

    collide_kernel<<<NBLK, NTPB>>>(centers, radii, d_lb, d_ln, out, n);
}

// round 6
// speedup vs baseline: 7.9126x; 1.1902x over previous
#include <cuda_runtime.h>
#include <cuda_bf16.h>

// One-kernel collision pipeline, 64 blocks x 128 threads (1 body/thread).
// Single software global barrier (after grid build); the prefix-offset
// dependency is handled by decoupled lookback on per-block packed sums
// (tag+data in ONE 64-bit word -> no fences). Narrow phase fused into the
// ring query; candidate/hit ranks from one packed scan. Cell counters are
// double-buffered by launch epoch parity so cleanup races with nothing.
//
// N=8192, BOX=112, radii in [0.5,1.0) -> rsum < 2.0 -> grid cell 2.0 (56x56);
// all AABB-overlapping pairs lie within the +-1 cell ring.
// Reference semantics reproduced exactly: row-major ascending (i,j) candidate
// order, cutoffs limit_broad=4N (broad) and limit_narrow=N (hits).

#define MAXN  8192
#define MAXB  (4 * MAXN)
#define GDIM  56
#define NCELL (GDIM * GDIM)
#define CAPC  20            // bodies/cell cap (avg 2.6; Poisson tail safe)
#define CAPR  32            // candidates/row cap (avg ~4; tail safe)
#define NBLK  64
#define NTPB  128
#define NTH   (NBLK * NTPB)

typedef unsigned long long ull;

__device__ unsigned     g_bar_cnt = 0;           // self-resetting
__device__ unsigned     g_bar_epoch = 0;         // +1 per launch (1 barrier)
__device__ int          g_cellcnt[2][NCELL];     // parity double buffer
__device__ float4       g_cellslot[NCELL * CAPC];
__device__ volatile ull g_flag[NBLK];            // (tag<<32)|(cnt<<16)|hit

__device__ __forceinline__ void global_barrier() {
    __syncthreads();
    if (threadIdx.x == 0) {
        volatile unsigned* ep = &g_bar_epoch;
        unsigned e = *ep;
        __threadfence();
        unsigned old = atomicAdd(&g_bar_cnt, 1u);
        if (old == gridDim.x - 1) {
            g_bar_cnt = 0;
            __threadfence();
            atomicAdd(&g_bar_epoch, 1u);
        } else {
            while (*ep == e) __nanosleep(16);
        }
        __threadfence();
    }
    __syncthreads();
}

// Exclusive block scan of packed (cnt<<32 | hit); total left in s_ws[NTPB/32].
__device__ __forceinline__ ull block_scan_excl(ull v, ull* s_ws) {
    const int t = threadIdx.x, lane = t & 31, wid = t >> 5;
    ull incl = v;
    #pragma unroll
    for (int o = 1; o < 32; o <<= 1) {
        ull x = __shfl_up_sync(0xFFFFFFFFu, incl, o);
        if (lane >= o) incl += x;
    }
    if (lane == 31) s_ws[wid] = incl;
    __syncthreads();
    if (wid == 0 && lane == 0) {
        ull run = 0;
        #pragma unroll
        for (int w = 0; w < NTPB / 32; w++) {
            ull x = s_ws[w];
            s_ws[w] = run;
            run += x;
        }
        s_ws[NTPB / 32] = run;
    }
    __syncthreads();
    return incl - v + s_ws[wid];
}

__global__ __launch_bounds__(NTPB)
void collide_kernel(const float2* __restrict__ c,
                    const float*  __restrict__ r,
                    const int*    __restrict__ d_lb,
                    const int*    __restrict__ d_ln,
                    float*        __restrict__ out, int n) {
    __shared__ ull s_ws[NTPB / 32 + 1];
    __shared__ ull s_pre;
    const int t   = threadIdx.x;
    const int bid = blockIdx.x;
    const int gid = bid * NTPB + t;

    // Epoch read happens before this block arrives at GB1, hence before any
    // possible increment (increment requires ALL blocks to have arrived).
    const unsigned E   = *(volatile unsigned*)&g_bar_epoch;
    const int      par = E & 1;

    // ---- P1: load body, copy centers to out, insert into grid ----
    float2 ci = make_float2(0.f, 0.f);
    float  ri = 0.f;
    int cx = 0, cy = 0;
    if (gid < n) {
        ci = c[gid];
        ri = r[gid];
        ((float2*)out)[gid] = ci;
        cx = min(GDIM - 1, max(0, (int)(ci.x * 0.5f)));
        cy = min(GDIM - 1, max(0, (int)(ci.y * 0.5f)));
        int cell = cy * GDIM + cx;
        int slot = atomicAdd(&g_cellcnt[par][cell], 1);
        if (slot < CAPC)
            g_cellslot[cell * CAPC + slot] =
                make_float4(ci.x, ci.y, ri, __int_as_float(gid));
    }
    global_barrier();   // GB1: grid built (the only global barrier)

    // ---- P2: prefetch 9 ring-cell counts (MLP), then query + narrow ----
    int keys[CAPR];          // (j<<1) | hit   -- local memory, L1-resident
    float hdx[CAPR], hdy[CAPR], hrs[CAPR];   // per-hit data (no reloads later)
    int cnt = 0, hitcnt = 0;
    if (gid < n) {
        int  cell9[9];
        int  cc9[9];
        #pragma unroll
        for (int s = 0; s < 9; s++) {
            int yy = cy + s / 3 - 1;
            int xx = cx + s % 3 - 1;
            bool v = (yy >= 0) & (yy < GDIM) & (xx >= 0) & (xx < GDIM);
            int cell = v ? yy * GDIM + xx : 0;
            cell9[s] = cell;
            cc9[s]   = v ? g_cellcnt[par][cell] : 0;   // 9 independent LDGs
        }
        #pragma unroll
        for (int s = 0; s < 9; s++) {
            int cc = min(cc9[s], CAPC);
            const float4* base = &g_cellslot[cell9[s] * CAPC];
            #pragma unroll 2
            for (int q = 0; q < cc; q++) {
                float4 b = base[q];
                int j = __float_as_int(b.w);
                if (j <= gid) continue;
                float rs = ri + b.z;
                float dx = b.x - ci.x;
                float dy = b.y - ci.y;
                if (fabsf(dx) <= rs && fabsf(dy) <= rs) {
                    if (cnt < CAPR) {
                        // depth>0  <=>  d2 + eps < rs^2  (exact equivalence)
                        float d2 = dx * dx + dy * dy + 1e-12f;
                        int hit = (d2 < rs * rs) ? 1 : 0;
                        keys[cnt] = (j << 1) | hit;
                        if (hit) {
                            hdx[cnt] = dx; hdy[cnt] = dy; hrs[cnt] = rs;
                            hitcnt++;
                        }
                    }
                    cnt++;
                }
            }
        }
        if (cnt > CAPR) cnt = CAPR;
    }

    // ---- P3: packed block scan + decoupled lookback (replaces barrier) ----
    ull excl = block_scan_excl(((ull)cnt << 32) | (unsigned)hitcnt, s_ws);
    if (t == 0) {
        ull btot = s_ws[NTPB / 32];
        unsigned bc = (unsigned)(btot >> 32);
        unsigned bh = (unsigned)(btot & 0xFFFFFFFFu);
        // single-word publish: tag + data, inherently ordered
        g_flag[bid] = ((ull)(E + 1) << 32) | ((ull)bc << 16) | (ull)bh;
        s_pre = 0;
    }
    __syncthreads();
    if (t < bid) {             // parallel lookback over predecessors
        ull w;
        do { w = g_flag[t]; } while ((unsigned)(w >> 32) != E + 1);
        ull contrib = ((w >> 16) & 0xFFFFull) << 32 | (w & 0xFFFFull);
        atomicAdd(&s_pre, contrib);
    }
    __syncthreads();
    const ull tot  = s_pre + excl;
    const int offc = (int)(tot >> 32);
    const int offh = (int)(tot & 0xFFFFFFFFu);
    const int limitb = min(*d_lb, MAXB);
    const int ln     = *d_ln;

    // clean the OTHER parity's counters (untouched this launch -> race-free)
    for (int idx = gid; idx < NCELL; idx += NTH) g_cellcnt[1 - par][idx] = 0;

    // ---- P4: resolve hits within both cutoffs (all data in registers/LMEM) --
    // Broad cutoff: sorted rank < limitb - offc. Dropped candidates are always
    // the highest ranks, so unmasked prefix sums stay exact for emitters.
    if (gid < n && offc < limitb && hitcnt > 0) {
        const int survive = min(cnt, limitb - offc);
        for (int k = 0; k < cnt; k++) {
            int key = keys[k];
            if (!(key & 1)) continue;
            int rank = 0, hrank = 0;
            #pragma unroll 4
            for (int m = 0; m < cnt; m++) {
                int km = keys[m];
                int lt = (km < key) ? 1 : 0;      // distinct j -> strict order
                rank  += lt;
                hrank += lt & km;                  // lt & hit-bit
            }
            if (rank >= survive) continue;         // broad cutoff
            if (offh + hrank >= ln) continue;      // narrow cutoff
            float dx = hdx[k], dy = hdy[k], rs = hrs[k];
            float dist = sqrtf(dx * dx + dy * dy + 1e-12f);
            float sc = 0.5f * (rs - dist) / dist;
            float ddx = sc * dx, ddy = sc * dy;
            int jv = key >> 1;
            atomicAdd(&out[2 * gid + 0], -ddx);
            atomicAdd(&out[2 * gid + 1], -ddy);
            atomicAdd(&out[2 * jv  + 0],  ddx);
            atomicAdd(&out[2 * jv  + 1],  ddy);
        }
    }
}

// ---------------------------------------------------------------------------
extern "C" void kernel_launch(void* const* d_in, const int* in_sizes, int n_in,
                              void* d_out, int out_size) {
    const float2* centers = (const float2*)d_in[0];
    const float*  radii   = (const float*)d_in[1];
    const int*    d_lb    = (const int*)d_in[2];
    const int*    d_ln    = (const int*)d_in[3];
    const int n = in_sizes[1];
    float* out = (float*)d_out;

    collide_kernel<<<NBLK, NTPB>>>(centers, radii, d_lb, d_ln, out, n);
}